// round 4
// baseline (speedup 1.0000x reference)
#include <cuda_runtime.h>

#define RADIAL 160
#define RPB 2                        // rows per block
#define ROW_F (RADIAL * 3)           // 480
#define NTHREADS (RADIAL * RPB)      // 320
#define F4_PER_BLOCK (RPB * ROW_F / 4)  // 240
#define HB 4                         // halo bins each side
#define SROW ((RADIAL + 2 * HB) * 3) // 504 floats (divisible by 4)

struct Params {
    float dt_offset;
    float dt_persist;
    float k, cc;
    float amount;
    float w[5];
    int   D;
    int   edge;
};

__device__ Params g_params;
__device__ float4 g_coef[RADIAL];   // fused advect+diffuse+fade coefficients

__global__ void prep_kernel(const float* __restrict__ offset,
                            const float* __restrict__ persistence,
                            const float* __restrict__ diffusion01,
                            const float* __restrict__ dt_seconds,
                            const float* __restrict__ amount01,
                            const float* __restrict__ spread01) {
    const int i = threadIdx.x;   // 160 threads, one per bin

    // Every thread recomputes scalar params (cheap, avoids broadcast sync).
    float dt = fminf(fmaxf(*dt_seconds, 0.0f), 0.05f);
    float dt_scale = dt * 60.0f;
    float off = (*offset) * dt_scale;
    float P   = powf(*persistence, dt_scale);
    float k   = 0.15f * (*diffusion01);
    float cc  = 1.0f - 2.0f * k;
    int   D   = (int)floorf(off);

    // Edge check: does floor(i + off) deviate from i + D for any valid source?
    float npi = (float)i + off;
    bool validi = (npi >= 0.0f) && (npi < (float)(RADIAL - 1));
    int lii = min(max((int)floorf(npi), 0), RADIAL - 2);
    int myedge = (validi && (lii != i + D)) ? 1 : 0;
    int edge = __syncthreads_or(myedge);

    if (i == 0) {
        g_params.dt_offset  = off;
        g_params.dt_persist = P;
        g_params.k  = k;
        g_params.cc = cc;
        g_params.D  = D;
        g_params.edge = edge;
        g_params.amount = fminf(fmaxf(*amount01, 0.0f), 1.0f);
        float spread = fminf(fmaxf(*spread01, 0.0f), 1.0f);
        float tight  = 1.0f - spread;
        g_params.w[0] = 0.5f + 0.4f * tight;
        g_params.w[1] = 0.2f * spread + 0.05f;
        g_params.w[2] = 0.12f * spread;
        g_params.w[3] = 0.06f * spread;
        g_params.w[4] = 0.02f * spread;
    }

    // Fused coefficient table for bin = i (valid whenever edge == 0):
    // out[bin] = fade[bin] * sum_d C_d[bin] * hclip[bin-D-2+d]
    const int bin = i;
    float fade = 1.0f;
    if (bin >= RADIAL - 8) {
        float tt = (float)(RADIAL - 1 - bin) * 0.125f;
        fade = tt * tt;
    }
    float c[4] = {0.0f, 0.0f, 0.0f, 0.0f};
    #pragma unroll
    for (int d = 0; d < 4; d++) {
        int s = bin - D - 2 + d;
        if (s < 0 || s >= RADIAL) continue;
        float nps = (float)s + off;                  // same fp ops as reference
        if (!(nps >= 0.0f && nps < (float)(RADIAL - 1))) continue;
        int   ls  = min(max((int)floorf(nps), 0), RADIAL - 2);
        float fr  = nps - (float)ls;
        float wls = (1.0f - fr) * P;
        float wrs = fr * P;
        // S[b][s]: wls at b==ls, wrs at b==ls+1
        float sb  = (ls == bin     ? wls : 0.0f) + (ls + 1 == bin     ? wrs : 0.0f);
        float sbm = 0.0f, sbp = 0.0f;
        if (bin >= 1)
            sbm = (ls == bin - 1 ? wls : 0.0f) + (ls + 1 == bin - 1 ? wrs : 0.0f);
        if (bin <= RADIAL - 2)
            sbp = (ls == bin + 1 ? wls : 0.0f) + (ls + 1 == bin + 1 ? wrs : 0.0f);
        c[d] = (cc * sb + k * (sbm + sbp)) * fade;
    }
    g_coef[bin] = make_float4(c[0], c[1], c[2], c[3]);
}

__global__ __launch_bounds__(NTHREADS)
void beat_pulse_kernel(const float* __restrict__ history,
                       const float* __restrict__ color_rgb,
                       float* __restrict__ out) {
    __shared__ float s1[RPB * SROW];     // clipped history, 4-bin zero halo per side
    __shared__ float s2[RPB * ROW_F];    // fallback scratch (edge path only)

    const int t = threadIdx.x;
    const long long base_row = (long long)blockIdx.x * RPB;

    // ---- zero halos (24 floats per row) ----
    if (t < RPB * 2 * HB * 3) {          // 48 threads
        int r = t / (2 * HB * 3);
        int j = t - r * (2 * HB * 3);
        int o = (j < HB * 3) ? j : (HB * 3 + ROW_F + (j - HB * 3));
        s1[r * SROW + o] = 0.0f;
    }

    // ---- Phase 1: coalesced float4 load + inject + clip01 -> SMEM ----
    if (t < F4_PER_BLOCK) {
        const float* gin = history + base_row * ROW_F;
        float4 v = ((const float4*)gin)[t];
        int row = t / (ROW_F / 4);
        int q   = t - row * (ROW_F / 4);
        int idx = q * 4;                 // scalar index within row

        float vals[4] = {v.x, v.y, v.z, v.w};
        if (idx < 15) {
            long long b = base_row + row;
            float amount = g_params.amount;
            float en[3];
            en[0] = color_rgb[b * 3 + 0] * amount;
            en[1] = color_rgb[b * 3 + 1] * amount;
            en[2] = color_rgb[b * 3 + 2] * amount;
            #pragma unroll
            for (int e = 0; e < 4; e++) {
                int sidx = idx + e;
                int bin  = sidx / 3;
                int ch   = sidx - bin * 3;
                if (bin < 5) vals[e] += en[ch] * g_params.w[bin];
            }
        }
        #pragma unroll
        for (int e = 0; e < 4; e++) vals[e] = fminf(fmaxf(vals[e], 0.0f), 1.0f);

        float4 o; o.x = vals[0]; o.y = vals[1]; o.z = vals[2]; o.w = vals[3];
        ((float4*)s1)[row * (SROW / 4) + (HB * 3 / 4) + q] = o;
    }
    __syncthreads();

    const int row = t / RADIAL;
    const int bin = t - row * RADIAL;
    const int D   = g_params.D;

    if (!g_params.edge) {
        // ---- Fast path: fused 4-tap banded operator, direct STG ----
        // tap0 = bin-D-2  -> halo index (bin-D-2+HB)*3 = (bin-D+2)*3
        int bh = min(max(bin - D + 2, 0), RADIAL + 2 * HB - 4);
        const float* q = s1 + row * SROW + bh * 3;
        float4 c = g_coef[bin];

        float o0 = c.x * q[0] + c.y * q[3] + c.z * q[6] + c.w * q[9];
        float o1 = c.x * q[1] + c.y * q[4] + c.z * q[7] + c.w * q[10];
        float o2 = c.x * q[2] + c.y * q[5] + c.z * q[8] + c.w * q[11];

        float* gout = out + (base_row + row) * ROW_F + bin * 3;
        gout[0] = o0; gout[1] = o1; gout[2] = o2;
    } else {
        // ---- Generic fallback (never taken for bench params) ----
        const float off = g_params.dt_offset;
        const float P   = g_params.dt_persist;
        const int sbase1 = row * SROW + HB * 3;   // logical bin 0 in s1
        const int sbase2 = row * ROW_F;

        float wk0 = 0.0f, wk1 = 0.0f, wk2 = 0.0f;
        #pragma unroll
        for (int d = -2; d <= 1; d++) {
            int i = bin - D + d;
            float np = (float)i + off;
            float lf = floorf(np);
            int   li = (int)lf;
            float fr = np - lf;
            bool vs = (i >= 0) & (i < RADIAL) & (np >= 0.0f) & (np < (float)(RADIAL - 1));
            float wl = (vs && li == bin)     ? (1.0f - fr) * P : 0.0f;
            float wr = (vs && li == bin - 1) ? fr * P          : 0.0f;
            float w = wl + wr;
            int a = sbase1 + min(max(i, 0), RADIAL - 1) * 3;
            wk0 += w * s1[a + 0];
            wk1 += w * s1[a + 1];
            wk2 += w * s1[a + 2];
        }
        s2[sbase2 + bin * 3 + 0] = wk0;
        s2[sbase2 + bin * 3 + 1] = wk1;
        s2[sbase2 + bin * 3 + 2] = wk2;
        __syncthreads();

        const float k  = g_params.k;
        const float cc = g_params.cc;
        float fade = 1.0f;
        if (bin >= RADIAL - 8) {
            float tt = (float)(RADIAL - 1 - bin) * 0.125f;
            fade = tt * tt;
        }
        float* gout = out + (base_row + row) * ROW_F + bin * 3;
        #pragma unroll
        for (int c = 0; c < 3; c++) {
            float xc = s2[sbase2 + bin * 3 + c];
            float xm = (bin > 0)          ? s2[sbase2 + (bin - 1) * 3 + c] : 0.0f;
            float xp = (bin < RADIAL - 1) ? s2[sbase2 + (bin + 1) * 3 + c] : 0.0f;
            gout[c] = (cc * xc + k * xm + k * xp) * fade;
        }
    }
}

extern "C" void kernel_launch(void* const* d_in, const int* in_sizes, int n_in,
                              void* d_out, int out_size) {
    const float* history     = (const float*)d_in[0];
    const float* color_rgb   = (const float*)d_in[1];
    const float* offset      = (const float*)d_in[2];
    const float* persistence = (const float*)d_in[3];
    const float* diffusion01 = (const float*)d_in[4];
    const float* dt_seconds  = (const float*)d_in[5];
    const float* amount01    = (const float*)d_in[6];
    const float* spread01    = (const float*)d_in[7];
    float* out = (float*)d_out;

    int B = in_sizes[0] / ROW_F;
    int grid = (B + RPB - 1) / RPB;

    prep_kernel<<<1, RADIAL>>>(offset, persistence, diffusion01, dt_seconds,
                               amount01, spread01);
    beat_pulse_kernel<<<grid, NTHREADS>>>(history, color_rgb, out);
}

// round 5
// speedup vs baseline: 1.0066x; 1.0066x over previous
#include <cuda_runtime.h>

#define RADIAL 160
#define RPB 2                        // rows per block
#define ROW_F (RADIAL * 3)           // 480
#define NTHREADS (RADIAL * RPB)      // 320
#define F4_PER_BLOCK (RPB * ROW_F / 4)  // 240
#define HB 4                         // halo bins each side
#define SROW ((RADIAL + 2 * HB) * 3) // 504 floats (divisible by 4)

struct Params {
    float dt_offset;
    float dt_persist;
    float k, cc;
    float amount;
    float w[5];
    int   D;
    int   edge;
};

__device__ Params g_params;
__device__ float4 g_coef[RADIAL];   // fused advect+diffuse+fade coefficients

__global__ void prep_kernel(const float* __restrict__ offset,
                            const float* __restrict__ persistence,
                            const float* __restrict__ diffusion01,
                            const float* __restrict__ dt_seconds,
                            const float* __restrict__ amount01,
                            const float* __restrict__ spread01) {
    const int i = threadIdx.x;   // 160 threads, one per bin

    // Every thread recomputes scalar params (cheap, avoids broadcast sync).
    float dt = fminf(fmaxf(*dt_seconds, 0.0f), 0.05f);
    float dt_scale = dt * 60.0f;
    float off = (*offset) * dt_scale;
    float P   = powf(*persistence, dt_scale);
    float k   = 0.15f * (*diffusion01);
    float cc  = 1.0f - 2.0f * k;
    int   D   = (int)floorf(off);

    // Edge check: does floor(i + off) deviate from i + D for any valid source?
    float npi = (float)i + off;
    bool validi = (npi >= 0.0f) && (npi < (float)(RADIAL - 1));
    int lii = min(max((int)floorf(npi), 0), RADIAL - 2);
    int myedge = (validi && (lii != i + D)) ? 1 : 0;
    int edge = __syncthreads_or(myedge);

    if (i == 0) {
        g_params.dt_offset  = off;
        g_params.dt_persist = P;
        g_params.k  = k;
        g_params.cc = cc;
        g_params.D  = D;
        g_params.edge = edge;
        g_params.amount = fminf(fmaxf(*amount01, 0.0f), 1.0f);
        float spread = fminf(fmaxf(*spread01, 0.0f), 1.0f);
        float tight  = 1.0f - spread;
        g_params.w[0] = 0.5f + 0.4f * tight;
        g_params.w[1] = 0.2f * spread + 0.05f;
        g_params.w[2] = 0.12f * spread;
        g_params.w[3] = 0.06f * spread;
        g_params.w[4] = 0.02f * spread;
    }

    // Fused coefficient table for bin = i (valid whenever edge == 0):
    // out[bin] = fade[bin] * sum_d C_d[bin] * hclip[bin-D-2+d]
    const int bin = i;
    float fade = 1.0f;
    if (bin >= RADIAL - 8) {
        float tt = (float)(RADIAL - 1 - bin) * 0.125f;
        fade = tt * tt;
    }
    float c[4] = {0.0f, 0.0f, 0.0f, 0.0f};
    #pragma unroll
    for (int d = 0; d < 4; d++) {
        int s = bin - D - 2 + d;
        if (s < 0 || s >= RADIAL) continue;
        float nps = (float)s + off;                  // same fp ops as reference
        if (!(nps >= 0.0f && nps < (float)(RADIAL - 1))) continue;
        int   ls  = min(max((int)floorf(nps), 0), RADIAL - 2);
        float fr  = nps - (float)ls;
        float wls = (1.0f - fr) * P;
        float wrs = fr * P;
        // S[b][s]: wls at b==ls, wrs at b==ls+1
        float sb  = (ls == bin     ? wls : 0.0f) + (ls + 1 == bin     ? wrs : 0.0f);
        float sbm = 0.0f, sbp = 0.0f;
        if (bin >= 1)
            sbm = (ls == bin - 1 ? wls : 0.0f) + (ls + 1 == bin - 1 ? wrs : 0.0f);
        if (bin <= RADIAL - 2)
            sbp = (ls == bin + 1 ? wls : 0.0f) + (ls + 1 == bin + 1 ? wrs : 0.0f);
        c[d] = (cc * sb + k * (sbm + sbp)) * fade;
    }
    g_coef[bin] = make_float4(c[0], c[1], c[2], c[3]);
}

__global__ __launch_bounds__(NTHREADS)
void beat_pulse_kernel(const float* __restrict__ history,
                       const float* __restrict__ color_rgb,
                       float* __restrict__ out) {
    __shared__ float s1[RPB * SROW];     // clipped history, 4-bin zero halo per side
    __shared__ float s2[RPB * ROW_F];    // fallback scratch (edge path only)

    const int t = threadIdx.x;
    const long long base_row = (long long)blockIdx.x * RPB;

    // ---- zero halos (24 floats per row) ----
    if (t < RPB * 2 * HB * 3) {          // 48 threads
        int r = t / (2 * HB * 3);
        int j = t - r * (2 * HB * 3);
        int o = (j < HB * 3) ? j : (HB * 3 + ROW_F + (j - HB * 3));
        s1[r * SROW + o] = 0.0f;
    }

    // ---- Phase 1: coalesced float4 load + inject + clip01 -> SMEM ----
    if (t < F4_PER_BLOCK) {
        const float* gin = history + base_row * ROW_F;
        float4 v = ((const float4*)gin)[t];
        int row = t / (ROW_F / 4);
        int q   = t - row * (ROW_F / 4);
        int idx = q * 4;                 // scalar index within row

        float vals[4] = {v.x, v.y, v.z, v.w};
        if (idx < 15) {
            long long b = base_row + row;
            float amount = g_params.amount;
            float en[3];
            en[0] = color_rgb[b * 3 + 0] * amount;
            en[1] = color_rgb[b * 3 + 1] * amount;
            en[2] = color_rgb[b * 3 + 2] * amount;
            #pragma unroll
            for (int e = 0; e < 4; e++) {
                int sidx = idx + e;
                int bin  = sidx / 3;
                int ch   = sidx - bin * 3;
                if (bin < 5) vals[e] += en[ch] * g_params.w[bin];
            }
        }
        #pragma unroll
        for (int e = 0; e < 4; e++) vals[e] = fminf(fmaxf(vals[e], 0.0f), 1.0f);

        float4 o; o.x = vals[0]; o.y = vals[1]; o.z = vals[2]; o.w = vals[3];
        ((float4*)s1)[row * (SROW / 4) + (HB * 3 / 4) + q] = o;
    }
    __syncthreads();

    const int row = t / RADIAL;
    const int bin = t - row * RADIAL;
    const int D   = g_params.D;

    if (!g_params.edge) {
        // ---- Fast path: fused 4-tap banded operator, direct STG ----
        // tap0 = bin-D-2  -> halo index (bin-D-2+HB)*3 = (bin-D+2)*3
        int bh = min(max(bin - D + 2, 0), RADIAL + 2 * HB - 4);
        const float* q = s1 + row * SROW + bh * 3;
        float4 c = g_coef[bin];

        float o0 = c.x * q[0] + c.y * q[3] + c.z * q[6] + c.w * q[9];
        float o1 = c.x * q[1] + c.y * q[4] + c.z * q[7] + c.w * q[10];
        float o2 = c.x * q[2] + c.y * q[5] + c.z * q[8] + c.w * q[11];

        float* gout = out + (base_row + row) * ROW_F + bin * 3;
        gout[0] = o0; gout[1] = o1; gout[2] = o2;
    } else {
        // ---- Generic fallback (never taken for bench params) ----
        const float off = g_params.dt_offset;
        const float P   = g_params.dt_persist;
        const int sbase1 = row * SROW + HB * 3;   // logical bin 0 in s1
        const int sbase2 = row * ROW_F;

        float wk0 = 0.0f, wk1 = 0.0f, wk2 = 0.0f;
        #pragma unroll
        for (int d = -2; d <= 1; d++) {
            int i = bin - D + d;
            float np = (float)i + off;
            float lf = floorf(np);
            int   li = (int)lf;
            float fr = np - lf;
            bool vs = (i >= 0) & (i < RADIAL) & (np >= 0.0f) & (np < (float)(RADIAL - 1));
            float wl = (vs && li == bin)     ? (1.0f - fr) * P : 0.0f;
            float wr = (vs && li == bin - 1) ? fr * P          : 0.0f;
            float w = wl + wr;
            int a = sbase1 + min(max(i, 0), RADIAL - 1) * 3;
            wk0 += w * s1[a + 0];
            wk1 += w * s1[a + 1];
            wk2 += w * s1[a + 2];
        }
        s2[sbase2 + bin * 3 + 0] = wk0;
        s2[sbase2 + bin * 3 + 1] = wk1;
        s2[sbase2 + bin * 3 + 2] = wk2;
        __syncthreads();

        const float k  = g_params.k;
        const float cc = g_params.cc;
        float fade = 1.0f;
        if (bin >= RADIAL - 8) {
            float tt = (float)(RADIAL - 1 - bin) * 0.125f;
            fade = tt * tt;
        }
        float* gout = out + (base_row + row) * ROW_F + bin * 3;
        #pragma unroll
        for (int c = 0; c < 3; c++) {
            float xc = s2[sbase2 + bin * 3 + c];
            float xm = (bin > 0)          ? s2[sbase2 + (bin - 1) * 3 + c] : 0.0f;
            float xp = (bin < RADIAL - 1) ? s2[sbase2 + (bin + 1) * 3 + c] : 0.0f;
            gout[c] = (cc * xc + k * xm + k * xp) * fade;
        }
    }
}

extern "C" void kernel_launch(void* const* d_in, const int* in_sizes, int n_in,
                              void* d_out, int out_size) {
    const float* history     = (const float*)d_in[0];
    const float* color_rgb   = (const float*)d_in[1];
    const float* offset      = (const float*)d_in[2];
    const float* persistence = (const float*)d_in[3];
    const float* diffusion01 = (const float*)d_in[4];
    const float* dt_seconds  = (const float*)d_in[5];
    const float* amount01    = (const float*)d_in[6];
    const float* spread01    = (const float*)d_in[7];
    float* out = (float*)d_out;

    int B = in_sizes[0] / ROW_F;
    int grid = (B + RPB - 1) / RPB;

    prep_kernel<<<1, RADIAL>>>(offset, persistence, diffusion01, dt_seconds,
                               amount01, spread01);
    beat_pulse_kernel<<<grid, NTHREADS>>>(history, color_rgb, out);
}